// round 6
// baseline (speedup 1.0000x reference)
#include <cuda_runtime.h>
#include <cuda_bf16.h>
#include <math.h>
#include <stdint.h>

#define EMBED 768
#define HEADS 12
#define HD    64
#define MLPD  3072
#define BATCH 4
#define SEQ   1024
#define ROWS  (BATCH*SEQ)
#define QKVW  (3*EMBED)
#define BH    (BATCH*HEADS)

typedef __nv_bfloat16 bf16;

// ------------------------- scratch ------------------------------------------
__device__ float g_h32 [ROWS*EMBED];
__device__ bf16  g_h_hi[ROWS*EMBED],  g_h_lo[ROWS*EMBED];
__device__ bf16  g_wqkvT_hi[QKVW*EMBED], g_wqkvT_lo[QKVW*EMBED];
__device__ bf16  g_woutT_hi[EMBED*EMBED], g_woutT_lo[EMBED*EMBED];
__device__ bf16  g_w1T_hi[MLPD*EMBED],  g_w1T_lo[MLPD*EMBED];
__device__ bf16  g_w2T_hi[EMBED*MLPD],  g_w2T_lo[EMBED*MLPD];
__device__ bf16  g_qkv_hi[ROWS*QKVW],   g_qkv_lo[ROWS*QKVW];
__device__ bf16  g_attn_hi[ROWS*EMBED], g_attn_lo[ROWS*EMBED];
__device__ float g_x2[ROWS*EMBED];
__device__ bf16  g_h2_hi[ROWS*EMBED],  g_h2_lo[ROWS*EMBED];
__device__ bf16  g_mid_hi[ROWS*MLPD],  g_mid_lo[ROWS*MLPD];

// ------------------------- helpers ------------------------------------------
__device__ __forceinline__ uint32_t smem_u32(const void* p){
    uint32_t a;
    asm("{ .reg .u64 t; cvta.to.shared.u64 t, %1; cvt.u32.u64 %0, t; }" : "=r"(a) : "l"(p));
    return a;
}
__device__ __forceinline__ void split_bf(float v, bf16& h, bf16& l){
    h = __float2bfloat16(v);
    l = __float2bfloat16(v - __bfloat162float(h));
}
__device__ __forceinline__ void cp16(uint32_t dst, const void* src){
    asm volatile("cp.async.cg.shared.global [%0], [%1], 16;" :: "r"(dst), "l"(src));
}
__device__ __forceinline__ void ldsm4(uint32_t* r, uint32_t a){
    asm volatile("ldmatrix.sync.aligned.m8n8.x4.shared.b16 {%0,%1,%2,%3}, [%4];"
        : "=r"(r[0]),"=r"(r[1]),"=r"(r[2]),"=r"(r[3]) : "r"(a));
}
__device__ __forceinline__ void ldsm4t(uint32_t* r, uint32_t a){
    asm volatile("ldmatrix.sync.aligned.m8n8.x4.trans.shared.b16 {%0,%1,%2,%3}, [%4];"
        : "=r"(r[0]),"=r"(r[1]),"=r"(r[2]),"=r"(r[3]) : "r"(a));
}
__device__ __forceinline__ void ldsm2(uint32_t* r, uint32_t a){
    asm volatile("ldmatrix.sync.aligned.m8n8.x2.shared.b16 {%0,%1}, [%2];"
        : "=r"(r[0]),"=r"(r[1]) : "r"(a));
}
__device__ __forceinline__ void mma16816(float* c, const uint32_t* a, const uint32_t* b){
    asm volatile("mma.sync.aligned.m16n8k16.row.col.f32.bf16.bf16.f32 "
        "{%0,%1,%2,%3}, {%4,%5,%6,%7}, {%8,%9}, {%0,%1,%2,%3};"
        : "+f"(c[0]),"+f"(c[1]),"+f"(c[2]),"+f"(c[3])
        : "r"(a[0]),"r"(a[1]),"r"(a[2]),"r"(a[3]), "r"(b[0]),"r"(b[1]));
}
__device__ __forceinline__ uint32_t pack_bf2(bf16 a, bf16 b){
    return (uint32_t)__bfloat16_as_ushort(a) | ((uint32_t)__bfloat16_as_ushort(b) << 16);
}
__device__ __forceinline__ void pack_split(float x, float y, uint32_t& hp, uint32_t& lp){
    bf16 hx, lx, hy, ly;
    split_bf(x, hx, lx); split_bf(y, hy, ly);
    hp = pack_bf2(hx, hy);
    lp = pack_bf2(lx, ly);
}

// ------------------------- weight transpose + split -------------------------
__global__ void tconv(const float* __restrict__ W, bf16* __restrict__ Thi, bf16* __restrict__ Tlo,
                      int K, int N)
{
    __shared__ float s[32][33];
    const int n0 = blockIdx.x * 32, k0 = blockIdx.y * 32;
    const int tx = threadIdx.x, ty = threadIdx.y;
    #pragma unroll
    for (int i = 0; i < 4; i++)
        s[ty + i*8][tx] = W[(size_t)(k0 + ty + i*8) * N + n0 + tx];
    __syncthreads();
    #pragma unroll
    for (int i = 0; i < 4; i++) {
        const int n = ty + i*8;
        float v = s[tx][n];
        bf16 h, l; split_bf(v, h, l);
        const size_t o = (size_t)(n0 + n) * K + k0 + tx;
        Thi[o] = h; Tlo[o] = l;
    }
}

// ------------------------- LayerNorm ----------------------------------------
__global__ __launch_bounds__(256) void ln_kernel(const float* __restrict__ x,
                                                 const float* __restrict__ g,
                                                 const float* __restrict__ b,
                                                 float* __restrict__ out32,
                                                 bf16* __restrict__ ohi,
                                                 bf16* __restrict__ olo)
{
    const int row = blockIdx.x;
    const int t = threadIdx.x;
    const float* xr = x + (size_t)row * EMBED;
    float v0 = xr[t], v1 = xr[t+256], v2 = xr[t+512];
    float s = v0+v1+v2, sq = v0*v0+v1*v1+v2*v2;
    #pragma unroll
    for (int off = 16; off; off >>= 1) {
        s  += __shfl_xor_sync(0xffffffffu, s,  off);
        sq += __shfl_xor_sync(0xffffffffu, sq, off);
    }
    __shared__ float red[16];
    const int w = t >> 5;
    if ((t & 31) == 0) { red[w] = s; red[8+w] = sq; }
    __syncthreads();
    float tot = 0.f, totq = 0.f;
    #pragma unroll
    for (int i = 0; i < 8; i++) { tot += red[i]; totq += red[8+i]; }
    const float mu = tot * (1.f/768.f);
    const float var = totq * (1.f/768.f) - mu*mu;
    const float rstd = rsqrtf(fmaxf(var, 0.f) + 1e-5f);
    const size_t o = (size_t)row * EMBED;
    #pragma unroll
    for (int i = 0; i < 3; i++) {
        const int c = t + i*256;
        const float v = (i==0?v0:(i==1?v1:v2));
        const float y = (v - mu) * rstd * g[c] + b[c];
        if (out32) out32[o + c] = y;
        bf16 h, l; split_bf(y, h, l);
        ohi[o + c] = h; olo[o + c] = l;
    }
}

// ------------------------- 128x128 hi/lo GEMM (2-stage) ---------------------
// EPI 2: f32 +bias+add1+add2   EPI 4: f32 +bias+add1
template<int EPI>
__global__ void __launch_bounds__(256, 2) gemm_mma(
    const bf16* __restrict__ Ahi, const bf16* __restrict__ Alo, int lda,
    const bf16* __restrict__ Bhi, const bf16* __restrict__ Blo, int ldb,
    float* __restrict__ C, int ldc,
    const float* __restrict__ bias, const float* __restrict__ add1, const float* __restrict__ add2,
    int K)
{
    constexpr int RS  = 80;
    constexpr int SA  = 128 * RS;
    constexpr int BUF = 4 * SA;

    extern __shared__ char sm[];
    const uint32_t smb = smem_u32(sm);

    const int tid  = threadIdx.x;
    const int wid  = tid >> 5, lane = tid & 31;
    const int warp_m = wid & 1, warp_n = wid >> 1;
    const int rowBase = blockIdx.y * 128;
    const int colBase = blockIdx.x * 128;

    float acc[4][4][4];
    #pragma unroll
    for (int mt = 0; mt < 4; mt++)
        #pragma unroll
        for (int nt = 0; nt < 4; nt++)
            #pragma unroll
            for (int i = 0; i < 4; i++) acc[mt][nt][i] = 0.f;

    auto load_chunk = [&](int c) {
        const uint32_t st = smb + (c & 1)*BUF;
        const int k0 = c * 32;
        #pragma unroll
        for (int i = 0; i < 4; i++) {
            const int t = tid + i*256;
            const int plane = t >> 9, rr = (t >> 2) & 127, cg = t & 3;
            const bf16* src = (plane ? Alo : Ahi) + (size_t)(rowBase + rr) * lda + k0 + cg*8;
            cp16(st + plane*SA + rr*RS + cg*16, src);
        }
        #pragma unroll
        for (int i = 0; i < 4; i++) {
            const int t = tid + i*256;
            const int plane = t >> 9, rr = (t >> 2) & 127, cg = t & 3;
            const bf16* src = (plane ? Blo : Bhi) + (size_t)(colBase + rr) * ldb + k0 + cg*8;
            cp16(st + 2*SA + plane*SA + rr*RS + cg*16, src);
        }
        asm volatile("cp.async.commit_group;");
    };

    load_chunk(0);
    const int NC = K / 32;
    for (int c = 0; c < NC; ++c) {
        asm volatile("cp.async.wait_group 0;" ::: "memory");
        __syncthreads();
        if (c + 1 < NC) load_chunk(c + 1);

        const uint32_t st = smb + (c & 1)*BUF;
        #pragma unroll
        for (int ks = 0; ks < 2; ks++) {
            uint32_t bh[4][2], bl[4][2];
            #pragma unroll
            for (int nt = 0; nt < 4; nt++) {
                const int row = warp_n*32 + nt*8 + (lane & 7);
                const int kb  = ks*32 + ((lane >> 3) & 1)*16;
                const uint32_t ad = st + 2*SA + row*RS + kb;
                ldsm2(bh[nt], ad);
                ldsm2(bl[nt], ad + SA);
            }
            #pragma unroll
            for (int mt = 0; mt < 4; mt++) {
                const int row = warp_m*64 + mt*16 + (lane & 15);
                const int kb  = ks*32 + (lane >> 4)*16;
                const uint32_t aad = st + row*RS + kb;
                uint32_t ah[4], al[4];
                ldsm4(ah, aad);
                ldsm4(al, aad + SA);
                #pragma unroll
                for (int nt = 0; nt < 4; nt++) {
                    mma16816(acc[mt][nt], ah, bh[nt]);
                    mma16816(acc[mt][nt], ah, bl[nt]);
                    mma16816(acc[mt][nt], al, bh[nt]);
                }
            }
        }
    }

    #pragma unroll
    for (int mt = 0; mt < 4; mt++) {
        #pragma unroll
        for (int nt = 0; nt < 4; nt++) {
            const int gr0 = rowBase + warp_m*64 + mt*16 + (lane >> 2);
            const int gc  = colBase + warp_n*32 + nt*8 + (lane & 3)*2;
            #pragma unroll
            for (int half = 0; half < 2; half++) {
                const int gr = gr0 + half*8;
                const size_t idx = (size_t)gr * ldc + gc;
                float v0 = acc[mt][nt][half*2 + 0];
                float v1 = acc[mt][nt][half*2 + 1];
                if (EPI == 2) {
                    v0 += bias[gc+0] + add1[idx+0] + add2[idx+0];
                    v1 += bias[gc+1] + add1[idx+1] + add2[idx+1];
                } else {
                    v0 += bias[gc+0] + add1[idx+0];
                    v1 += bias[gc+1] + add1[idx+1];
                }
                *(float2*)(C + idx) = make_float2(v0, v1);
            }
        }
    }
}

// ------------------------- 128x256 hi/lo GEMM (3-stage, 512 thr) ------------
// EPI 1: hi/lo split (QS: cols<768 scaled by 0.125)   EPI 3: split(gelu(+bias))
template<int EPI, bool QS>
__global__ void __launch_bounds__(512, 1) gemm_big(
    const bf16* __restrict__ Ahi, const bf16* __restrict__ Alo, int lda,
    const bf16* __restrict__ Bhi, const bf16* __restrict__ Blo, int ldb,
    bf16* __restrict__ Chi, bf16* __restrict__ Clo, int ldc,
    const float* __restrict__ bias,
    int K)
{
    constexpr int RS   = 80;
    constexpr int SAP  = 128 * RS;        // 10240, A plane
    constexpr int SBP  = 256 * RS;        // 20480, B plane
    constexpr int STG  = 2*SAP + 2*SBP;   // 61440 per stage

    extern __shared__ char sm[];
    const uint32_t smb = smem_u32(sm);

    const int tid  = threadIdx.x;
    const int wid  = tid >> 5, lane = tid & 31;
    const int warp_m = wid & 1, warp_n = wid >> 1;    // 0..1, 0..7
    const int rowBase = blockIdx.y * 128;
    const int colBase = blockIdx.x * 256;

    float acc[4][4][4];
    #pragma unroll
    for (int mt = 0; mt < 4; mt++)
        #pragma unroll
        for (int nt = 0; nt < 4; nt++)
            #pragma unroll
            for (int i = 0; i < 4; i++) acc[mt][nt][i] = 0.f;

    auto load_chunk = [&](int c) {
        const uint32_t st = smb + (uint32_t)(c % 3) * STG;
        const int k0 = c * 32;
        // A: 1024 cp16 (2 planes x 128 rows x 4 groups)
        #pragma unroll
        for (int i = 0; i < 2; i++) {
            const int t = tid + i*512;
            const int plane = t >> 9, rr = (t >> 2) & 127, cg = t & 3;
            const bf16* src = (plane ? Alo : Ahi) + (size_t)(rowBase + rr) * lda + k0 + cg*8;
            cp16(st + plane*SAP + rr*RS + cg*16, src);
        }
        // B: 2048 cp16 (2 planes x 256 rows x 4 groups)
        #pragma unroll
        for (int i = 0; i < 4; i++) {
            const int t = tid + i*512;
            const int plane = t >> 10, rr = (t >> 2) & 255, cg = t & 3;
            const bf16* src = (plane ? Blo : Bhi) + (size_t)(colBase + rr) * ldb + k0 + cg*8;
            cp16(st + 2*SAP + plane*SBP + rr*RS + cg*16, src);
        }
        asm volatile("cp.async.commit_group;");
    };

    const int NC = K / 32;
    load_chunk(0);
    load_chunk(1);
    for (int c = 0; c < NC; ++c) {
        if (c + 1 < NC) asm volatile("cp.async.wait_group 1;" ::: "memory");
        else            asm volatile("cp.async.wait_group 0;" ::: "memory");
        __syncthreads();
        if (c + 2 < NC) load_chunk(c + 2);

        const uint32_t st = smb + (uint32_t)(c % 3) * STG;
        #pragma unroll
        for (int ks = 0; ks < 2; ks++) {
            uint32_t bh[4][2], bl[4][2];
            #pragma unroll
            for (int nt = 0; nt < 4; nt++) {
                const int row = warp_n*32 + nt*8 + (lane & 7);
                const int kb  = ks*32 + ((lane >> 3) & 1)*16;
                const uint32_t ad = st + 2*SAP + row*RS + kb;
                ldsm2(bh[nt], ad);
                ldsm2(bl[nt], ad + SBP);
            }
            #pragma unroll
            for (int mt = 0; mt < 4; mt++) {
                const int row = warp_m*64 + mt*16 + (lane & 15);
                const int kb  = ks*32 + (lane >> 4)*16;
                const uint32_t aad = st + row*RS + kb;
                uint32_t ah[4], al[4];
                ldsm4(ah, aad);
                ldsm4(al, aad + SAP);
                #pragma unroll
                for (int nt = 0; nt < 4; nt++) {
                    mma16816(acc[mt][nt], ah, bh[nt]);
                    mma16816(acc[mt][nt], ah, bl[nt]);
                    mma16816(acc[mt][nt], al, bh[nt]);
                }
            }
        }
    }

    #pragma unroll
    for (int mt = 0; mt < 4; mt++) {
        #pragma unroll
        for (int nt = 0; nt < 4; nt++) {
            const int gr0 = rowBase + warp_m*64 + mt*16 + (lane >> 2);
            const int gc  = colBase + warp_n*32 + nt*8 + (lane & 3)*2;
            #pragma unroll
            for (int half = 0; half < 2; half++) {
                const int gr = gr0 + half*8;
                const size_t idx = (size_t)gr * ldc + gc;
                float v0 = acc[mt][nt][half*2 + 0];
                float v1 = acc[mt][nt][half*2 + 1];
                if (EPI == 3) {
                    v0 += bias[gc+0];
                    v1 += bias[gc+1];
                    v0 = 0.5f * v0 * (1.f + erff(v0 * 0.70710678118654752f));
                    v1 = 0.5f * v1 * (1.f + erff(v1 * 0.70710678118654752f));
                }
                if (QS && gc < EMBED) { v0 *= 0.125f; v1 *= 0.125f; }
                uint32_t hp, lp;
                pack_split(v0, v1, hp, lp);
                *(uint32_t*)(Chi + idx) = hp;
                *(uint32_t*)(Clo + idx) = lp;
            }
        }
    }
}

// ------------------------- fused flash attention ----------------------------
__global__ void __launch_bounds__(256) flash_attn(
    const bf16* __restrict__ qh_g, const bf16* __restrict__ ql_g,
    bf16* __restrict__ Ohi, bf16* __restrict__ Olo)
{
    extern __shared__ char sm[];
    const uint32_t smb = smem_u32(sm);
    const int tid = threadIdx.x, lane = tid & 31, wid = tid >> 5;
    const int qt = blockIdx.x;
    const int b  = blockIdx.y / HEADS, h = blockIdx.y % HEADS;
    const size_t gbase = (size_t)b * SEQ * QKVW;
    const int hoff = h * HD;

    #pragma unroll
    for (int i = 0; i < 8; i++) {
        const int t = tid + i*256;
        const int plane = t >> 10, rem = t & 1023, r = rem >> 3, cg = rem & 7;
        const bf16* src = (plane ? ql_g : qh_g) + gbase + (size_t)(qt*128 + r)*QKVW + hoff + cg*8;
        cp16(smb + plane*18432 + (uint32_t)(r*144 + cg*16), src);
    }
    auto load_kv = [&](int j) {
        const uint32_t dst = smb + 36864 + (j & 1)*36864;
        #pragma unroll
        for (int i = 0; i < 8; i++) {
            const int t = tid + i*256;
            const int q4 = t >> 9, rem = t & 511, r = rem >> 3, cg = rem & 7;
            const bf16* src = ((q4 & 1) ? ql_g : qh_g) + gbase
                + (size_t)(j*64 + r)*QKVW + EMBED + (q4 >> 1)*EMBED + hoff + cg*8;
            cp16(dst + (uint32_t)(q4*9216 + r*144 + cg*16), src);
        }
        asm volatile("cp.async.commit_group;");
    };
    load_kv(0);

    const int warprow = wid * 16;
    float m0 = -1e30f, m1 = -1e30f, l0 = 0.f, l1 = 0.f;
    float o[8][4];
    #pragma unroll
    for (int nt = 0; nt < 8; nt++)
        #pragma unroll
        for (int i = 0; i < 4; i++) o[nt][i] = 0.f;

    for (int j = 0; j < 16; j++) {
        asm volatile("cp.async.wait_group 0;" ::: "memory");
        __syncthreads();
        if (j < 15) load_kv(j + 1);
        const uint32_t st = smb + 36864 + (j & 1)*36864;

        float s[8][4];
        #pragma unroll
        for (int nt = 0; nt < 8; nt++)
            #pragma unroll
            for (int i = 0; i < 4; i++) s[nt][i] = 0.f;
        #pragma unroll
        for (int ks = 0; ks < 4; ks++) {
            uint32_t qh[4], ql[4];
            const uint32_t qa = smb + (uint32_t)((warprow + (lane & 15))*144 + ks*32 + (lane >> 4)*16);
            ldsm4(qh, qa);
            ldsm4(ql, qa + 18432);
            #pragma unroll
            for (int nt = 0; nt < 8; nt++) {
                uint32_t kh[2], kl[2];
                const uint32_t ka = st + (uint32_t)((nt*8 + (lane & 7))*144 + ks*32 + ((lane >> 3) & 1)*16);
                ldsm2(kh, ka);
                ldsm2(kl, ka + 9216);
                mma16816(s[nt], qh, kh);
                mma16816(s[nt], qh, kl);
                mma16816(s[nt], ql, kh);
            }
        }

        float mt0 = s[0][0], mt1 = s[0][2];
        #pragma unroll
        for (int nt = 0; nt < 8; nt++) {
            mt0 = fmaxf(mt0, fmaxf(s[nt][0], s[nt][1]));
            mt1 = fmaxf(mt1, fmaxf(s[nt][2], s[nt][3]));
        }
        mt0 = fmaxf(mt0, __shfl_xor_sync(0xffffffffu, mt0, 1));
        mt0 = fmaxf(mt0, __shfl_xor_sync(0xffffffffu, mt0, 2));
        mt1 = fmaxf(mt1, __shfl_xor_sync(0xffffffffu, mt1, 1));
        mt1 = fmaxf(mt1, __shfl_xor_sync(0xffffffffu, mt1, 2));
        const float mn0 = fmaxf(m0, mt0), mn1 = fmaxf(m1, mt1);
        const float a0 = __expf(m0 - mn0), a1 = __expf(m1 - mn1);
        float rs0 = 0.f, rs1 = 0.f;
        #pragma unroll
        for (int nt = 0; nt < 8; nt++) {
            s[nt][0] = __expf(s[nt][0] - mn0); rs0 += s[nt][0];
            s[nt][1] = __expf(s[nt][1] - mn0); rs0 += s[nt][1];
            s[nt][2] = __expf(s[nt][2] - mn1); rs1 += s[nt][2];
            s[nt][3] = __expf(s[nt][3] - mn1); rs1 += s[nt][3];
        }
        rs0 += __shfl_xor_sync(0xffffffffu, rs0, 1);
        rs0 += __shfl_xor_sync(0xffffffffu, rs0, 2);
        rs1 += __shfl_xor_sync(0xffffffffu, rs1, 1);
        rs1 += __shfl_xor_sync(0xffffffffu, rs1, 2);
        l0 = l0 * a0 + rs0;  l1 = l1 * a1 + rs1;
        m0 = mn0;  m1 = mn1;
        #pragma unroll
        for (int nt = 0; nt < 8; nt++) {
            o[nt][0] *= a0; o[nt][1] *= a0;
            o[nt][2] *= a1; o[nt][3] *= a1;
        }

        uint32_t ph[4][4], pl[4][4];
        #pragma unroll
        for (int ks = 0; ks < 4; ks++) {
            pack_split(s[2*ks][0],   s[2*ks][1],   ph[ks][0], pl[ks][0]);
            pack_split(s[2*ks][2],   s[2*ks][3],   ph[ks][1], pl[ks][1]);
            pack_split(s[2*ks+1][0], s[2*ks+1][1], ph[ks][2], pl[ks][2]);
            pack_split(s[2*ks+1][2], s[2*ks+1][3], ph[ks][3], pl[ks][3]);
        }

        #pragma unroll
        for (int ks = 0; ks < 4; ks++) {
            #pragma unroll
            for (int ntp = 0; ntp < 4; ntp++) {
                uint32_t vh[4], vl[4];
                const uint32_t va = st + 18432
                    + (uint32_t)((ks*16 + ((lane >> 3) & 1)*8 + (lane & 7))*144
                                 + ntp*32 + (lane >> 4)*16);
                ldsm4t(vh, va);
                ldsm4t(vl, va + 9216);
                mma16816(o[2*ntp],   ph[ks], &vh[0]);
                mma16816(o[2*ntp],   ph[ks], &vl[0]);
                mma16816(o[2*ntp],   pl[ks], &vh[0]);
                mma16816(o[2*ntp+1], ph[ks], &vh[2]);
                mma16816(o[2*ntp+1], ph[ks], &vl[2]);
                mma16816(o[2*ntp+1], pl[ks], &vh[2]);
            }
        }
    }

    const float rl0 = 1.f / l0, rl1 = 1.f / l1;
    const int gr = b*SEQ + qt*128 + warprow + (lane >> 2);
    #pragma unroll
    for (int nt = 0; nt < 8; nt++) {
        const int gc = hoff + nt*8 + (lane & 3)*2;
        const size_t i0 = (size_t)gr * EMBED + gc;
        const size_t i1 = i0 + (size_t)8 * EMBED;
        uint32_t hp, lp;
        pack_split(o[nt][0]*rl0, o[nt][1]*rl0, hp, lp);
        *(uint32_t*)(Ohi + i0) = hp;  *(uint32_t*)(Olo + i0) = lp;
        pack_split(o[nt][2]*rl1, o[nt][3]*rl1, hp, lp);
        *(uint32_t*)(Ohi + i1) = hp;  *(uint32_t*)(Olo + i1) = lp;
    }
}

// ------------------------- host ---------------------------------------------
extern "C" void kernel_launch(void* const* d_in, const int* in_sizes, int n_in,
                              void* d_out, int out_size)
{
    const float* x     = (const float*)d_in[0];
    const float* ln1_g = (const float*)d_in[1];
    const float* ln1_b = (const float*)d_in[2];
    const float* w_qkv = (const float*)d_in[3];
    const float* w_out = (const float*)d_in[4];
    const float* b_out = (const float*)d_in[5];
    const float* ln2_g = (const float*)d_in[6];
    const float* ln2_b = (const float*)d_in[7];
    const float* w1    = (const float*)d_in[8];
    const float* b1    = (const float*)d_in[9];
    const float* w2    = (const float*)d_in[10];
    const float* b2    = (const float*)d_in[11];
    float* out = (float*)d_out;

    float *h32, *x2;
    bf16 *h_hi,*h_lo,*wqkvT_hi,*wqkvT_lo,*woutT_hi,*woutT_lo,*w1T_hi,*w1T_lo,*w2T_hi,*w2T_lo;
    bf16 *qkv_hi,*qkv_lo,*attn_hi,*attn_lo,*h2_hi,*h2_lo,*mid_hi,*mid_lo;
    cudaGetSymbolAddress((void**)&h32, g_h32);
    cudaGetSymbolAddress((void**)&h_hi, g_h_hi);       cudaGetSymbolAddress((void**)&h_lo, g_h_lo);
    cudaGetSymbolAddress((void**)&wqkvT_hi, g_wqkvT_hi); cudaGetSymbolAddress((void**)&wqkvT_lo, g_wqkvT_lo);
    cudaGetSymbolAddress((void**)&woutT_hi, g_woutT_hi); cudaGetSymbolAddress((void**)&woutT_lo, g_woutT_lo);
    cudaGetSymbolAddress((void**)&w1T_hi, g_w1T_hi);   cudaGetSymbolAddress((void**)&w1T_lo, g_w1T_lo);
    cudaGetSymbolAddress((void**)&w2T_hi, g_w2T_hi);   cudaGetSymbolAddress((void**)&w2T_lo, g_w2T_lo);
    cudaGetSymbolAddress((void**)&qkv_hi, g_qkv_hi);   cudaGetSymbolAddress((void**)&qkv_lo, g_qkv_lo);
    cudaGetSymbolAddress((void**)&attn_hi, g_attn_hi); cudaGetSymbolAddress((void**)&attn_lo, g_attn_lo);
    cudaGetSymbolAddress((void**)&x2, g_x2);
    cudaGetSymbolAddress((void**)&h2_hi, g_h2_hi);     cudaGetSymbolAddress((void**)&h2_lo, g_h2_lo);
    cudaGetSymbolAddress((void**)&mid_hi, g_mid_hi);   cudaGetSymbolAddress((void**)&mid_lo, g_mid_lo);

    const int SMG  = 2 * 4 * 128 * 80;     // 81920 (2-stage 128x128)
    const int SMB  = 3 * 61440;            // 184320 (3-stage 128x256)
    const int SMF  = 110592;
    cudaFuncSetAttribute(gemm_big<1,true >, cudaFuncAttributeMaxDynamicSharedMemorySize, SMB);
    cudaFuncSetAttribute(gemm_big<3,false>, cudaFuncAttributeMaxDynamicSharedMemorySize, SMB);
    cudaFuncSetAttribute(gemm_mma<2>,       cudaFuncAttributeMaxDynamicSharedMemorySize, SMG);
    cudaFuncSetAttribute(gemm_mma<4>,       cudaFuncAttributeMaxDynamicSharedMemorySize, SMG);
    cudaFuncSetAttribute(flash_attn,        cudaFuncAttributeMaxDynamicSharedMemorySize, SMF);

    tconv<<<dim3(QKVW/32, EMBED/32), dim3(32,8)>>>(w_qkv, wqkvT_hi, wqkvT_lo, EMBED, QKVW);
    tconv<<<dim3(EMBED/32, EMBED/32), dim3(32,8)>>>(w_out, woutT_hi, woutT_lo, EMBED, EMBED);
    tconv<<<dim3(MLPD/32, EMBED/32), dim3(32,8)>>>(w1, w1T_hi, w1T_lo, EMBED, MLPD);
    tconv<<<dim3(EMBED/32, MLPD/32), dim3(32,8)>>>(w2, w2T_hi, w2T_lo, MLPD, EMBED);

    // 1) h = LN1(x)
    ln_kernel<<<ROWS, 256>>>(x, ln1_g, ln1_b, h32, h_hi, h_lo);

    // 2) qkv = h @ w_qkv   (Q columns pre-scaled by 1/8)
    gemm_big<1,true><<<dim3(QKVW/256, ROWS/128), 512, SMB>>>(
        h_hi, h_lo, EMBED, wqkvT_hi, wqkvT_lo, EMBED,
        qkv_hi, qkv_lo, QKVW, nullptr, EMBED);

    // 3) fused flash attention
    flash_attn<<<dim3(SEQ/128, BH), 256, SMF>>>(qkv_hi, qkv_lo, attn_hi, attn_lo);

    // 4) x2 = x + h + attn @ w_out + b_out
    gemm_mma<2><<<dim3(EMBED/128, ROWS/128), 256, SMG>>>(
        attn_hi, attn_lo, EMBED, woutT_hi, woutT_lo, EMBED,
        x2, EMBED, b_out, x, h32, EMBED);

    // 5) h2 = LN2(x2)
    ln_kernel<<<ROWS, 256>>>(x2, ln2_g, ln2_b, nullptr, h2_hi, h2_lo);

    // 6) mid = gelu(h2 @ w1 + b1)
    gemm_big<3,false><<<dim3(MLPD/256, ROWS/128), 512, SMB>>>(
        h2_hi, h2_lo, EMBED, w1T_hi, w1T_lo, EMBED,
        mid_hi, mid_lo, MLPD, b1, EMBED);

    // 7) out = x2 + mid @ w2 + b2
    gemm_mma<4><<<dim3(EMBED/128, ROWS/128), 256, SMG>>>(
        mid_hi, mid_lo, MLPD, w2T_hi, w2T_lo, MLPD,
        out, EMBED, b2, x2, nullptr, MLPD);
}